// round 6
// baseline (speedup 1.0000x reference)
#include <cuda_runtime.h>
#include <cuda_bf16.h>

// Problem constants (fixed by reference setup_inputs)
#define B_   4
#define C_   32
#define H_   96
#define W_   312
#define D_   48
#define HW_  (H_ * W_)
#define W4_  (W_ / 4)           // 78 float4 per row
#define REP_PITCH (W_ + 4)      // 316 floats per shifted replica
#define ROWS 4                  // h-rows per tile
#define NTHREADS 320            // 4*78 = 312 active compute lanes
#define TILES (B_ * C_ * (H_ / ROWS))   // 3072
#define PERSISTENT_BLOCKS (148 * 6)     // 888: exactly one resident wave
#define PAD_VALUE 1.0f

// Persistent blocks; each loops over (bc, row-group) tiles.
//  - Each r row staged in shared 4x; replica s shifted right by s elements, so
//    window r[w-d .. w-d+3] is one ALIGNED, conflict-free LDS.128 from
//    replica (d & 3) at element (w - 4*(d>>2)).
//  - l float4 in registers, reused for all 48 d.
//  - 4 consecutive h rows are contiguous in the output plane [H, W]: the
//    block's 312 lanes store one contiguous 4992B span per d-plane.
//  - Threads with w >= D never hit padding/clamp: pure-sub fast path.
__global__ __launch_bounds__(NTHREADS) void cost_volume_kernel(
    const float* __restrict__ l_fmap,
    const float* __restrict__ r_fmap,
    float* __restrict__ out)
{
    __shared__ float rep[ROWS][4][REP_PITCH];

    const int tid = threadIdx.x;
    const int row = tid / W4_;          // valid only for tid < 312
    const int w4  = tid - row * W4_;
    const int w   = w4 * 4;
    const bool active = (tid < ROWS * W4_);

    for (int tile = blockIdx.x; tile < TILES; tile += PERSISTENT_BLOCKS) {
        const int hb = tile % (H_ / ROWS);
        const int bc = tile / (H_ / ROWS);
        const int h0 = hb * ROWS;

        const long long in_off = (long long)bc * HW_ + (long long)h0 * W_;
        const float* r_g = r_fmap + in_off;

        // Fill shifted replicas: rep[rr][s][j+s] = r[rr*W + j]   (4992 elems)
        for (int i = tid; i < ROWS * 4 * W_; i += NTHREADS) {
            const int rr  = i / (4 * W_);
            const int rem = i - rr * (4 * W_);
            const int s   = rem / W_;
            const int j   = rem - s * W_;
            rep[rr][s][j + s] = r_g[rr * W_ + j];
        }
        __syncthreads();

        if (active) {
            const float4 l4 = *reinterpret_cast<const float4*>(
                l_fmap + in_off + row * W_ + w);

            float* outp = out + (long long)bc * (D_ * HW_)
                              + (long long)(h0 + row) * W_ + w;
            const float* reprow0 = &rep[row][0][0];

            if (w >= D_) {
                // Fast path: no padding, no clamp ever (w - 4q >= 48 - 44 = 4)
                #pragma unroll
                for (int q = 0; q < D_ / 4; ++q) {
                    const int base = w - 4 * q;
                    #pragma unroll
                    for (int s = 0; s < 4; ++s) {
                        const int d = 4 * q + s;
                        const float4 r4 = *reinterpret_cast<const float4*>(
                            reprow0 + s * REP_PITCH + base);
                        float4 v;
                        v.x = l4.x - r4.x;
                        v.y = l4.y - r4.y;
                        v.z = l4.z - r4.z;
                        v.w = l4.w - r4.w;
                        __stcs(reinterpret_cast<float4*>(outp + (long long)d * HW_), v);
                    }
                }
            } else {
                // Boundary path: masked selects + clamped base
                #pragma unroll
                for (int q = 0; q < D_ / 4; ++q) {
                    const int base_raw = w - 4 * q;
                    const int base = base_raw < 0 ? 0 : base_raw;
                    #pragma unroll
                    for (int s = 0; s < 4; ++s) {
                        const int d = 4 * q + s;
                        const float4 r4 = *reinterpret_cast<const float4*>(
                            reprow0 + s * REP_PITCH + base);
                        float4 v;
                        v.x = (w + 0 >= d) ? (l4.x - r4.x) : PAD_VALUE;
                        v.y = (w + 1 >= d) ? (l4.y - r4.y) : PAD_VALUE;
                        v.z = (w + 2 >= d) ? (l4.z - r4.z) : PAD_VALUE;
                        v.w = (w + 3 >= d) ? (l4.w - r4.w) : PAD_VALUE;
                        __stcs(reinterpret_cast<float4*>(outp + (long long)d * HW_), v);
                    }
                }
            }
        }
        __syncthreads();   // smem reuse guard before next tile's fill
    }
}

extern "C" void kernel_launch(void* const* d_in, const int* in_sizes, int n_in,
                              void* d_out, int out_size)
{
    const float* l_fmap = (const float*)d_in[0];
    const float* r_fmap = (const float*)d_in[1];
    float* out = (float*)d_out;

    cost_volume_kernel<<<PERSISTENT_BLOCKS, NTHREADS>>>(l_fmap, r_fmap, out);
}

// round 8
// speedup vs baseline: 1.1610x; 1.1610x over previous
#include <cuda_runtime.h>
#include <cuda_bf16.h>

// Problem constants (fixed by reference setup_inputs)
#define B_   4
#define C_   32
#define H_   96
#define W_   312
#define D_   48
#define HW_  (H_ * W_)
#define W4_  (W_ / 4)           // 78 float4 per row
#define REP_PITCH (W_ + 4)      // 316 floats per shifted replica
#define ROWS 4                  // h-rows per tile
#define NTHREADS 320            // 4*78 = 312 active compute lanes
#define DHALF_Q 6               // 6 q-groups (24 disparities) per block
#define PAD_VALUE 1.0f

// One block per (bc, 4-row group, D-half). Splitting D in half doubles the
// grid (3072 -> 6144) at constant concurrency (888 resident blocks), cutting
// wave-quantization tail from ~15% to ~1.2%.
//  - Each r row staged in shared 4x; replica s shifted right by s elements, so
//    window r[w-d .. w-d+3] is one ALIGNED, conflict-free LDS.128 from
//    replica (d & 3) at element (w - 4*(d>>2)).
//  - l float4 in registers, reused for 24 disparities.
//  - 4 consecutive h rows are contiguous in the output plane [H, W]: the
//    block's 312 lanes store one contiguous 4992B span per d-plane.
__global__ __launch_bounds__(NTHREADS) void cost_volume_kernel(
    const float* __restrict__ l_fmap,
    const float* __restrict__ r_fmap,
    float* __restrict__ out)
{
    const int bid  = blockIdx.x;            // 0 .. 6143
    const int half = bid & 1;               // D-half: q in [6*half, 6*half+6)
    const int tile = bid >> 1;              // 0 .. 3071
    const int hb   = tile % (H_ / ROWS);
    const int bc   = tile / (H_ / ROWS);
    const int h0   = hb * ROWS;
    const int q0   = half * DHALF_Q;

    __shared__ float rep[ROWS][4][REP_PITCH];

    const long long in_off = (long long)bc * HW_ + (long long)h0 * W_;
    const float* r_g = r_fmap + in_off;

    // Fill shifted replicas: rep[rr][s][j+s] = r[rr*W + j]   (4992 elems)
    for (int i = threadIdx.x; i < ROWS * 4 * W_; i += NTHREADS) {
        const int rr  = i / (4 * W_);
        const int rem = i - rr * (4 * W_);
        const int s   = rem / W_;
        const int j   = rem - s * W_;
        rep[rr][s][j + s] = r_g[rr * W_ + j];
    }
    __syncthreads();

    const int tid = threadIdx.x;
    if (tid >= ROWS * W4_) return;          // 312 active lanes
    const int row = tid / W4_;
    const int w4  = tid - row * W4_;
    const int w   = w4 * 4;

    const float4 l4 = *reinterpret_cast<const float4*>(
        l_fmap + in_off + row * W_ + w);

    // Output [B, C, D, H, W]: base for (bc, h0+row, w); per-d stride HW_
    float* outp = out + (long long)bc * (D_ * HW_)
                      + (long long)(h0 + row) * W_ + w;
    const float* reprow0 = &rep[row][0][0]; // replica s at reprow0 + s*REP_PITCH

    #pragma unroll
    for (int qq = 0; qq < DHALF_Q; ++qq) {  // 6 groups of 4 disparities
        const int q = q0 + qq;
        const int base_raw = w - 4 * q;
        const int base = base_raw < 0 ? 0 : base_raw;   // clamped (masked anyway)
        #pragma unroll
        for (int s = 0; s < 4; ++s) {
            const int d = 4 * q + s;
            const float4 r4 = *reinterpret_cast<const float4*>(
                reprow0 + s * REP_PITCH + base);
            float4 v;
            v.x = (w + 0 >= d) ? (l4.x - r4.x) : PAD_VALUE;
            v.y = (w + 1 >= d) ? (l4.y - r4.y) : PAD_VALUE;
            v.z = (w + 2 >= d) ? (l4.z - r4.z) : PAD_VALUE;
            v.w = (w + 3 >= d) ? (l4.w - r4.w) : PAD_VALUE;
            __stcs(reinterpret_cast<float4*>(outp + (long long)d * HW_), v);
        }
    }
}

extern "C" void kernel_launch(void* const* d_in, const int* in_sizes, int n_in,
                              void* d_out, int out_size)
{
    const float* l_fmap = (const float*)d_in[0];
    const float* r_fmap = (const float*)d_in[1];
    float* out = (float*)d_out;

    const int blocks = B_ * C_ * (H_ / ROWS) * 2;   // 6144
    cost_volume_kernel<<<blocks, NTHREADS>>>(l_fmap, r_fmap, out);
}

// round 9
// speedup vs baseline: 1.1800x; 1.0164x over previous
#include <cuda_runtime.h>
#include <cuda_bf16.h>

// Problem constants (fixed by reference setup_inputs)
#define B_   4
#define C_   32
#define H_   96
#define W_   312
#define D_   48
#define HW_  (H_ * W_)
#define W4_  (W_ / 4)           // 78 float4 per row
#define REP_PITCH (W_ + 4)      // 316 floats per shifted replica
#define ROWS 4                  // h-rows per tile
#define NTHREADS 320            // 4*78 = 312 active compute lanes
#define DHALF_Q 6               // 6 q-groups (24 disparities) per block
#define PAD_VALUE 1.0f

// One block per (bc, 4-row group, D-half). Grid 6144 at 888 resident blocks
// -> 6.92 waves (tail ~1%).
//  - Each r row staged in shared 4x; replica s shifted right by s elements, so
//    window r[w-d .. w-d+3] is one ALIGNED, conflict-free LDS.128 from
//    replica (d & 3) at element (w - 4*(d>>2)).
//  - Fill is division-free: thread tid (<312) owns element j=tid of each of
//    the 4 rows: 4 LDG, each broadcast to 4 replicas via registers = 16 STS.
//  - l float4 in registers, reused for 24 disparities.
//  - Block's 312 lanes store one contiguous 4992B span per d-plane.
__global__ __launch_bounds__(NTHREADS) void cost_volume_kernel(
    const float* __restrict__ l_fmap,
    const float* __restrict__ r_fmap,
    float* __restrict__ out)
{
    const int bid  = blockIdx.x;            // 0 .. 6143
    const int half = bid & 1;               // D-half: q in [6*half, 6*half+6)
    const int tile = bid >> 1;              // 0 .. 3071
    const int hb   = tile % (H_ / ROWS);
    const int bc   = tile / (H_ / ROWS);
    const int h0   = hb * ROWS;
    const int q0   = half * DHALF_Q;

    __shared__ float rep[ROWS][4][REP_PITCH];

    const long long in_off = (long long)bc * HW_ + (long long)h0 * W_;
    const float* r_g = r_fmap + in_off;

    const int tid = threadIdx.x;

    // Division-free fill: thread tid (<312) owns column j = tid of all 4 rows.
    if (tid < W_) {
        #pragma unroll
        for (int rr = 0; rr < ROWS; ++rr) {
            const float rv = r_g[rr * W_ + tid];
            #pragma unroll
            for (int s = 0; s < 4; ++s)
                rep[rr][s][tid + s] = rv;
        }
    }
    __syncthreads();

    if (tid >= ROWS * W4_) return;          // 312 active lanes
    const int row = tid / W4_;
    const int w4  = tid - row * W4_;
    const int w   = w4 * 4;

    const float4 l4 = *reinterpret_cast<const float4*>(
        l_fmap + in_off + row * W_ + w);

    // Output [B, C, D, H, W]: base for (bc, h0+row, w); per-d stride HW_
    float* outp = out + (long long)bc * (D_ * HW_)
                      + (long long)(h0 + row) * W_ + w;
    const float* reprow0 = &rep[row][0][0]; // replica s at reprow0 + s*REP_PITCH

    #pragma unroll
    for (int qq = 0; qq < DHALF_Q; ++qq) {  // 6 groups of 4 disparities
        const int q = q0 + qq;
        const int base_raw = w - 4 * q;
        const int base = base_raw < 0 ? 0 : base_raw;   // clamped (masked anyway)
        #pragma unroll
        for (int s = 0; s < 4; ++s) {
            const int d = 4 * q + s;
            const float4 r4 = *reinterpret_cast<const float4*>(
                reprow0 + s * REP_PITCH + base);
            float4 v;
            v.x = (w + 0 >= d) ? (l4.x - r4.x) : PAD_VALUE;
            v.y = (w + 1 >= d) ? (l4.y - r4.y) : PAD_VALUE;
            v.z = (w + 2 >= d) ? (l4.z - r4.z) : PAD_VALUE;
            v.w = (w + 3 >= d) ? (l4.w - r4.w) : PAD_VALUE;
            __stcs(reinterpret_cast<float4*>(outp + (long long)d * HW_), v);
        }
    }
}

extern "C" void kernel_launch(void* const* d_in, const int* in_sizes, int n_in,
                              void* d_out, int out_size)
{
    const float* l_fmap = (const float*)d_in[0];
    const float* r_fmap = (const float*)d_in[1];
    float* out = (float*)d_out;

    const int blocks = B_ * C_ * (H_ / ROWS) * 2;   // 6144
    cost_volume_kernel<<<blocks, NTHREADS>>>(l_fmap, r_fmap, out);
}